// round 16
// baseline (speedup 1.0000x reference)
#include <cuda_runtime.h>
#include <cuda_fp16.h>
#include <math.h>
#include <stdint.h>

#define B_   16
#define T_   243
#define J_   17
#define D_   257
#define E_   256
#define W_   3
#define KW_  7
#define ROWS (B_ * T_ * J_)   // 66096
#define MTILES ((ROWS + 127) / 128)   // 517
#define WBLK  256

// Scratch
__device__ __half g_s[(size_t)ROWS * E_];
__device__ __half g_w[3 * E_ * E_];
__device__ __half g_qh[(size_t)ROWS * E_];
__device__ __half g_kh[(size_t)ROWS * E_];
__device__ __half g_vh[(size_t)ROWS * E_];

// ---------------------------------------------------------------------------
// Kernel 1: fused weight-convert (blocks [0,WBLK)) + Lorentz log-map.
// ---------------------------------------------------------------------------
__global__ void prep_kernel(const float* __restrict__ x,
                            const float* __restrict__ Wq,
                            const float* __restrict__ Wk,
                            const float* __restrict__ Wv)
{
    if (blockIdx.x < WBLK) {
        int i = blockIdx.x * 256 + threadIdx.x;
        g_w[i]           = __float2half_rn(Wq[i]);
        g_w[E_*E_ + i]   = __float2half_rn(Wk[i]);
        g_w[2*E_*E_ + i] = __float2half_rn(Wv[i]);
        return;
    }

    int gw = (blockIdx.x - WBLK) * 8 + (threadIdx.x >> 5);
    if (gw >= ROWS) return;
    int lane = threadIdx.x & 31;

    int bj = gw / T_;
    int t  = gw - bj * T_;
    int b  = bj / J_;
    int j  = bj - b * J_;
    size_t base = ((size_t)(b * T_ + t) * J_ + j) * D_;

    float s8[8];
    float ss = 0.f;
    #pragma unroll
    for (int i = 0; i < 8; i++) {
        s8[i] = x[base + 1 + i * 32 + lane];
        ss = fmaf(s8[i], s8[i], ss);
    }
    #pragma unroll
    for (int o = 16; o > 0; o >>= 1) ss += __shfl_xor_sync(0xffffffffu, ss, o);

    float xn = fmaxf(sqrtf(ss), 1e-7f);
    float xt = x[base];
    float scale = acoshf(fmaxf(xt, 1.0f + 1e-7f)) / xn;

    size_t obase = (size_t)gw * E_;
    #pragma unroll
    for (int i = 0; i < 8; i++)
        g_s[obase + i * 32 + lane] = __float2half_rn(scale * s8[i]);
}

// ---------------------------------------------------------------------------
// Kernel 2: fused QKV GEMM, fp16 mma.sync single-term, 3-stage cp.async.
//   Block 128x128, warp 64x32, GBK=64, 2 CTA/SM, fp16 out. (protected, 86us)
// ---------------------------------------------------------------------------
#define GSTR   144
#define OFF_B  (128 * GSTR)
#define BUFSZ  (256 * GSTR)
#define GEMM_SMEM (3 * BUFSZ)

__device__ __forceinline__ void mma_f16(float* c, const uint32_t* a, const uint32_t* b)
{
    asm volatile(
        "mma.sync.aligned.m16n8k16.row.col.f32.f16.f16.f32 "
        "{%0,%1,%2,%3}, {%4,%5,%6,%7}, {%8,%9}, {%0,%1,%2,%3};"
        : "+f"(c[0]), "+f"(c[1]), "+f"(c[2]), "+f"(c[3])
        : "r"(a[0]), "r"(a[1]), "r"(a[2]), "r"(a[3]), "r"(b[0]), "r"(b[1]));
}

__device__ __forceinline__ void ldsm4(uint32_t* r, uint32_t a)
{
    asm volatile("ldmatrix.sync.aligned.m8n8.x4.shared.b16 {%0,%1,%2,%3}, [%4];"
                 : "=r"(r[0]), "=r"(r[1]), "=r"(r[2]), "=r"(r[3]) : "r"(a));
}

__device__ __forceinline__ void cp16(uint32_t dst, const void* src, uint32_t sz)
{
    asm volatile("cp.async.cg.shared.global [%0], [%1], 16, %2;"
                 :: "r"(dst), "l"(src), "r"(sz) : "memory");
}

__global__ __launch_bounds__(256, 2) void qkv_gemm_tc(
    const float* __restrict__ bq, const float* __restrict__ bk,
    const float* __restrict__ bv)
{
    extern __shared__ char dynsm[];
    uint32_t smem = (uint32_t)__cvta_generic_to_shared(dynsm);

    int bn0 = blockIdx.x * 128;           // fast: 6 N-tiles share A in L2
    int bm0 = blockIdx.y * 128;
    int which = bn0 >> 8;
    int ncol0 = bn0 & 255;

    const __half* Wm  = g_w + (size_t)which * E_ * E_;
    const float* bias = (which == 0) ? bq : (which == 1) ? bk : bv;
    __half*      outp = (which == 0) ? g_qh : (which == 1) ? g_kh : g_vh;

    int tid  = threadIdx.x;
    int w    = tid >> 5;
    int lane = tid & 31;
    int m_off = (w >> 2) * 64;
    int n_off = (w & 3) * 32;
    int lg = lane >> 2;
    int lt = lane & 3;

    int sub = lane >> 3;
    int r8  = lane & 7;
    uint32_t aoff[4], boff[2];
    #pragma unroll
    for (int mi = 0; mi < 4; mi++)
        aoff[mi] = (uint32_t)((m_off + mi * 16 + (sub & 1) * 8 + r8) * GSTR
                              + (sub >> 1) * 16);
    #pragma unroll
    for (int nt = 0; nt < 2; nt++)
        boff[nt] = (uint32_t)((n_off + nt * 16 + (sub >> 1) * 8 + r8) * GSTR
                              + (sub & 1) * 16);

    float acc[4][4][4];
    #pragma unroll
    for (int mi = 0; mi < 4; mi++)
        #pragma unroll
        for (int ni = 0; ni < 4; ni++)
            #pragma unroll
            for (int c = 0; c < 4; c++) acc[mi][ni][c] = 0.f;

    auto prefetch = [&](int it) {
        uint32_t buf = smem + (uint32_t)(it % 3) * BUFSZ;
        int k0 = it * 64;
        #pragma unroll
        for (int r = 0; r < 4; r++) {
            int idx = tid + 256 * r;
            int row = idx >> 3;
            int q   = idx & 7;
            uint32_t doff = (uint32_t)(row * GSTR + q * 16);
            int grow = bm0 + row;
            uint32_t sz = (grow < ROWS) ? 16u : 0u;
            int ar = (grow < ROWS) ? grow : (ROWS - 1);
            size_t ga = (size_t)ar * E_ + k0 + q * 8;
            cp16(buf + doff, &g_s[ga], sz);
            size_t gb = (size_t)(ncol0 + row) * E_ + k0 + q * 8;
            cp16(buf + OFF_B + doff, &Wm[gb], 16u);
        }
        asm volatile("cp.async.commit_group;" ::: "memory");
    };

    prefetch(0);
    prefetch(1);

    #pragma unroll 1
    for (int c = 0; c < 4; c++) {
        if (c < 3) asm volatile("cp.async.wait_group 1;" ::: "memory");
        else       asm volatile("cp.async.wait_group 0;" ::: "memory");
        __syncthreads();
        if (c + 2 < 4) prefetch(c + 2);

        uint32_t buf = smem + (uint32_t)(c % 3) * BUFSZ;
        uint32_t Ap = buf, Bp = buf + OFF_B;

        #pragma unroll
        for (int ks = 0; ks < 4; ks++) {
            uint32_t kadd = (uint32_t)(ks * 32);
            uint32_t af[4][4];
            #pragma unroll
            for (int mi = 0; mi < 4; mi++)
                ldsm4(af[mi], Ap + aoff[mi] + kadd);
            #pragma unroll
            for (int nt = 0; nt < 2; nt++) {
                uint32_t th[4];
                ldsm4(th, Bp + boff[nt] + kadd);
                #pragma unroll
                for (int mi = 0; mi < 4; mi++) {
                    mma_f16(acc[mi][nt*2],   af[mi], &th[0]);
                    mma_f16(acc[mi][nt*2+1], af[mi], &th[2]);
                }
            }
        }
    }

    // epilogue: bias (fp32) + fp16 packed store
    #pragma unroll
    for (int mi = 0; mi < 4; mi++) {
        int row0 = bm0 + m_off + mi * 16 + lg;
        #pragma unroll
        for (int ni = 0; ni < 4; ni++) {
            int col = ncol0 + n_off + ni * 8 + lt * 2;
            float b0 = bias[col], b1 = bias[col + 1];
            if (row0 < ROWS) {
                __half2 h = __floats2half2_rn(acc[mi][ni][0] + b0, acc[mi][ni][1] + b1);
                *reinterpret_cast<__half2*>(&outp[(size_t)row0 * E_ + col]) = h;
            }
            if (row0 + 8 < ROWS) {
                __half2 h = __floats2half2_rn(acc[mi][ni][2] + b0, acc[mi][ni][3] + b1);
                *reinterpret_cast<__half2*>(&outp[(size_t)(row0 + 8) * E_ + col]) = h;
            }
        }
    }
}

// ---------------------------------------------------------------------------
// Kernel 3: window-7 attention + exp-map. TT=32 with 512 threads (16 warps,
// 2 rows/warp — same per-warp profile as the proven R12 loop; halo amortized).
// ---------------------------------------------------------------------------
#define TT 32
#define STRIP (TT + 2 * W_)   // 38
#define ATHREADS 512

__global__ __launch_bounds__(ATHREADS) void attn_kernel(const float* __restrict__ tau,
                                                        float* __restrict__ out)
{
    __shared__ __half sK[STRIP * E_];   // 19456 B
    __shared__ __half sV[STRIP * E_];   // 19456 B

    int t0 = blockIdx.x * TT;
    int bj = blockIdx.y;
    int base_row = bj * T_;
    int tid = threadIdx.x;

    for (int i = tid; i < STRIP * (E_ / 8); i += ATHREADS) {
        int r  = i >> 5;
        int c8 = i & 31;
        int tt = min(max(t0 - W_ + r, 0), T_ - 1);
        size_t g = (size_t)(base_row + tt) * E_ + c8 * 8;
        *reinterpret_cast<uint4*>(&sK[r * E_ + c8 * 8]) =
            *reinterpret_cast<const uint4*>(&g_kh[g]);
        *reinterpret_cast<uint4*>(&sV[r * E_ + c8 * 8]) =
            *reinterpret_cast<const uint4*>(&g_vh[g]);
    }
    __syncthreads();

    int warp = tid >> 5, lane = tid & 31;
    float inv_scale = 1.0f / (16.0f * fmaxf(tau[0], 0.001f));

    #pragma unroll
    for (int s = 0; s < 2; s++) {
        int t = t0 + warp * 2 + s;
        if (t >= T_) continue;
        int lrow = t - t0;

        uint4 qu = *reinterpret_cast<const uint4*>(&g_qh[(size_t)(base_row + t) * E_ + lane * 8]);
        __half2* q2 = reinterpret_cast<__half2*>(&qu);

        float dot[KW_];
        #pragma unroll
        for (int w = 0; w < KW_; w++) {
            uint4 ku = *reinterpret_cast<const uint4*>(&sK[(lrow + w) * E_ + lane * 8]);
            __half2* k2 = reinterpret_cast<__half2*>(&ku);
            __half2 pa = __hmul2(q2[0], k2[0]);
            pa = __hfma2(q2[1], k2[1], pa);
            __half2 pb = __hmul2(q2[2], k2[2]);
            pb = __hfma2(q2[3], k2[3], pb);
            float2 fa = __half22float2(pa);
            float2 fb = __half22float2(pb);
            float d = (fa.x + fa.y) + (fb.x + fb.y);
            #pragma unroll
            for (int o = 16; o > 0; o >>= 1) d += __shfl_xor_sync(0xffffffffu, d, o);
            dot[w] = d;
        }

        float m = -1e30f, logit[KW_];
        #pragma unroll
        for (int w = 0; w < KW_; w++) {
            int tt = t + w - W_;
            bool valid = (tt >= 0) && (tt < T_);
            logit[w] = valid ? dot[w] * inv_scale : -1e30f;
            m = fmaxf(m, logit[w]);
        }
        float e[KW_], esum = 0.f;
        #pragma unroll
        for (int w = 0; w < KW_; w++) {
            int tt = t + w - W_;
            bool valid = (tt >= 0) && (tt < T_);
            e[w] = valid ? __expf(logit[w] - m) : 0.f;
            esum += e[w];
        }
        float inv_esum = 1.0f / esum;

        float agg[8] = {0.f, 0.f, 0.f, 0.f, 0.f, 0.f, 0.f, 0.f};
        #pragma unroll
        for (int w = 0; w < KW_; w++) {
            int tt = t + w - W_;
            if (tt >= 0 && tt < T_) {
                float wt = e[w] * inv_esum;
                uint4 vu = *reinterpret_cast<const uint4*>(&sV[(lrow + w) * E_ + lane * 8]);
                __half2* v2 = reinterpret_cast<__half2*>(&vu);
                #pragma unroll
                for (int p = 0; p < 4; p++) {
                    float2 vf = __half22float2(v2[p]);
                    agg[p*2]   = fmaf(wt, vf.x, agg[p*2]);
                    agg[p*2+1] = fmaf(wt, vf.y, agg[p*2+1]);
                }
            }
        }

        float ss = 0.f;
        #pragma unroll
        for (int i = 0; i < 8; i++) ss = fmaf(agg[i], agg[i], ss);
        #pragma unroll
        for (int o = 16; o > 0; o >>= 1) ss += __shfl_xor_sync(0xffffffffu, ss, o);

        float n = fmaxf(sqrtf(ss), 1e-7f);
        float coef = sinhf(n) / n;
        float ch   = coshf(n);

        int b = bj / J_;
        int j = bj - b * J_;
        size_t obase = ((size_t)(b * T_ + t) * J_ + j) * D_;
        #pragma unroll
        for (int i = 0; i < 8; i++)
            out[obase + 1 + lane * 8 + i] = coef * agg[i];
        if (lane == 0) out[obase] = ch;
    }
}

// ---------------------------------------------------------------------------
extern "C" void kernel_launch(void* const* d_in, const int* in_sizes, int n_in,
                              void* d_out, int out_size)
{
    const float* x    = (const float*)d_in[0];
    // d_in[1] = vel_seq (unused by reference)
    const float* tau  = (const float*)d_in[2];
    const float* Wq   = (const float*)d_in[3];
    const float* bq   = (const float*)d_in[4];
    const float* Wk   = (const float*)d_in[5];
    const float* bk   = (const float*)d_in[6];
    const float* Wv   = (const float*)d_in[7];
    const float* bv   = (const float*)d_in[8];
    float* out = (float*)d_out;

    prep_kernel<<<WBLK + (ROWS + 7) / 8, 256>>>(x, Wq, Wk, Wv);

    cudaFuncSetAttribute(qkv_gemm_tc,
                         cudaFuncAttributeMaxDynamicSharedMemorySize, GEMM_SMEM);
    dim3 g2(6, MTILES);
    qkv_gemm_tc<<<g2, 256, GEMM_SMEM>>>(bq, bk, bv);

    dim3 g3((T_ + TT - 1) / TT, B_ * J_);
    attn_kernel<<<g3, ATHREADS>>>(tau, out);
}

// round 17
// speedup vs baseline: 1.0375x; 1.0375x over previous
#include <cuda_runtime.h>
#include <cuda_fp16.h>
#include <math.h>
#include <stdint.h>

#define B_   16
#define T_   243
#define J_   17
#define D_   257
#define E_   256
#define W_   3
#define KW_  7
#define ROWS (B_ * T_ * J_)   // 66096
#define MTILES ((ROWS + 127) / 128)   // 517
#define WBLK  256

// Scratch
__device__ __half g_s[(size_t)ROWS * E_];
__device__ __half g_w[3 * E_ * E_];
__device__ __half g_qh[(size_t)ROWS * E_];
__device__ __half g_kh[(size_t)ROWS * E_];
__device__ __half g_vh[(size_t)ROWS * E_];

// ---------------------------------------------------------------------------
// Kernel 1: fused weight-convert (blocks [0,WBLK)) + Lorentz log-map.
//   Logmap: 2 rows per warp, interleaved, to hide reduce/MUFU latency.
// ---------------------------------------------------------------------------
__global__ void prep_kernel(const float* __restrict__ x,
                            const float* __restrict__ Wq,
                            const float* __restrict__ Wk,
                            const float* __restrict__ Wv)
{
    if (blockIdx.x < WBLK) {
        int i = blockIdx.x * 256 + threadIdx.x;
        g_w[i]           = __float2half_rn(Wq[i]);
        g_w[E_*E_ + i]   = __float2half_rn(Wk[i]);
        g_w[2*E_*E_ + i] = __float2half_rn(Wv[i]);
        return;
    }

    int gw0 = (blockIdx.x - WBLK) * 16 + (threadIdx.x >> 5) * 2;
    int lane = threadIdx.x & 31;

    size_t base[2];
    bool valid[2];
    #pragma unroll
    for (int r = 0; r < 2; r++) {
        int gw = gw0 + r;
        valid[r] = (gw < ROWS);
        int gc = valid[r] ? gw : 0;
        int bj = gc / T_;
        int t  = gc - bj * T_;
        int b  = bj / J_;
        int j  = bj - b * J_;
        base[r] = ((size_t)(b * T_ + t) * J_ + j) * D_;
    }

    // front-batched loads for both rows (MLP 16)
    float s8[2][8];
    #pragma unroll
    for (int r = 0; r < 2; r++)
        #pragma unroll
        for (int i = 0; i < 8; i++)
            s8[r][i] = x[base[r] + 1 + i * 32 + lane];
    float xt0 = x[base[0]];
    float xt1 = x[base[1]];

    // two independent reduce chains, interleaved
    float ss0 = 0.f, ss1 = 0.f;
    #pragma unroll
    for (int i = 0; i < 8; i++) {
        ss0 = fmaf(s8[0][i], s8[0][i], ss0);
        ss1 = fmaf(s8[1][i], s8[1][i], ss1);
    }
    #pragma unroll
    for (int o = 16; o > 0; o >>= 1) {
        ss0 += __shfl_xor_sync(0xffffffffu, ss0, o);
        ss1 += __shfl_xor_sync(0xffffffffu, ss1, o);
    }

    float scale0 = acoshf(fmaxf(xt0, 1.0f + 1e-7f)) / fmaxf(sqrtf(ss0), 1e-7f);
    float scale1 = acoshf(fmaxf(xt1, 1.0f + 1e-7f)) / fmaxf(sqrtf(ss1), 1e-7f);

    #pragma unroll
    for (int r = 0; r < 2; r++) {
        if (!valid[r]) continue;
        float sc = (r == 0) ? scale0 : scale1;
        size_t obase = (size_t)(gw0 + r) * E_;
        #pragma unroll
        for (int i = 0; i < 8; i++)
            g_s[obase + i * 32 + lane] = __float2half_rn(sc * s8[r][i]);
    }
}

// ---------------------------------------------------------------------------
// Kernel 2: fused QKV GEMM, fp16 mma.sync single-term, 3-stage cp.async.
//   Block 128x128, warp 64x32, GBK=64, 2 CTA/SM, fp16 out.
//   (protected — at the sm_103a mma.sync quarter-rate HMMA ceiling, 86us)
// ---------------------------------------------------------------------------
#define GSTR   144
#define OFF_B  (128 * GSTR)
#define BUFSZ  (256 * GSTR)
#define GEMM_SMEM (3 * BUFSZ)

__device__ __forceinline__ void mma_f16(float* c, const uint32_t* a, const uint32_t* b)
{
    asm volatile(
        "mma.sync.aligned.m16n8k16.row.col.f32.f16.f16.f32 "
        "{%0,%1,%2,%3}, {%4,%5,%6,%7}, {%8,%9}, {%0,%1,%2,%3};"
        : "+f"(c[0]), "+f"(c[1]), "+f"(c[2]), "+f"(c[3])
        : "r"(a[0]), "r"(a[1]), "r"(a[2]), "r"(a[3]), "r"(b[0]), "r"(b[1]));
}

__device__ __forceinline__ void ldsm4(uint32_t* r, uint32_t a)
{
    asm volatile("ldmatrix.sync.aligned.m8n8.x4.shared.b16 {%0,%1,%2,%3}, [%4];"
                 : "=r"(r[0]), "=r"(r[1]), "=r"(r[2]), "=r"(r[3]) : "r"(a));
}

__device__ __forceinline__ void cp16(uint32_t dst, const void* src, uint32_t sz)
{
    asm volatile("cp.async.cg.shared.global [%0], [%1], 16, %2;"
                 :: "r"(dst), "l"(src), "r"(sz) : "memory");
}

__global__ __launch_bounds__(256, 2) void qkv_gemm_tc(
    const float* __restrict__ bq, const float* __restrict__ bk,
    const float* __restrict__ bv)
{
    extern __shared__ char dynsm[];
    uint32_t smem = (uint32_t)__cvta_generic_to_shared(dynsm);

    int bn0 = blockIdx.x * 128;           // fast: 6 N-tiles share A in L2
    int bm0 = blockIdx.y * 128;
    int which = bn0 >> 8;
    int ncol0 = bn0 & 255;

    const __half* Wm  = g_w + (size_t)which * E_ * E_;
    const float* bias = (which == 0) ? bq : (which == 1) ? bk : bv;
    __half*      outp = (which == 0) ? g_qh : (which == 1) ? g_kh : g_vh;

    int tid  = threadIdx.x;
    int w    = tid >> 5;
    int lane = tid & 31;
    int m_off = (w >> 2) * 64;
    int n_off = (w & 3) * 32;
    int lg = lane >> 2;
    int lt = lane & 3;

    int sub = lane >> 3;
    int r8  = lane & 7;
    uint32_t aoff[4], boff[2];
    #pragma unroll
    for (int mi = 0; mi < 4; mi++)
        aoff[mi] = (uint32_t)((m_off + mi * 16 + (sub & 1) * 8 + r8) * GSTR
                              + (sub >> 1) * 16);
    #pragma unroll
    for (int nt = 0; nt < 2; nt++)
        boff[nt] = (uint32_t)((n_off + nt * 16 + (sub >> 1) * 8 + r8) * GSTR
                              + (sub & 1) * 16);

    float acc[4][4][4];
    #pragma unroll
    for (int mi = 0; mi < 4; mi++)
        #pragma unroll
        for (int ni = 0; ni < 4; ni++)
            #pragma unroll
            for (int c = 0; c < 4; c++) acc[mi][ni][c] = 0.f;

    auto prefetch = [&](int it) {
        uint32_t buf = smem + (uint32_t)(it % 3) * BUFSZ;
        int k0 = it * 64;
        #pragma unroll
        for (int r = 0; r < 4; r++) {
            int idx = tid + 256 * r;
            int row = idx >> 3;
            int q   = idx & 7;
            uint32_t doff = (uint32_t)(row * GSTR + q * 16);
            int grow = bm0 + row;
            uint32_t sz = (grow < ROWS) ? 16u : 0u;
            int ar = (grow < ROWS) ? grow : (ROWS - 1);
            size_t ga = (size_t)ar * E_ + k0 + q * 8;
            cp16(buf + doff, &g_s[ga], sz);
            size_t gb = (size_t)(ncol0 + row) * E_ + k0 + q * 8;
            cp16(buf + OFF_B + doff, &Wm[gb], 16u);
        }
        asm volatile("cp.async.commit_group;" ::: "memory");
    };

    prefetch(0);
    prefetch(1);

    #pragma unroll 1
    for (int c = 0; c < 4; c++) {
        if (c < 3) asm volatile("cp.async.wait_group 1;" ::: "memory");
        else       asm volatile("cp.async.wait_group 0;" ::: "memory");
        __syncthreads();
        if (c + 2 < 4) prefetch(c + 2);

        uint32_t buf = smem + (uint32_t)(c % 3) * BUFSZ;
        uint32_t Ap = buf, Bp = buf + OFF_B;

        #pragma unroll
        for (int ks = 0; ks < 4; ks++) {
            uint32_t kadd = (uint32_t)(ks * 32);
            uint32_t af[4][4];
            #pragma unroll
            for (int mi = 0; mi < 4; mi++)
                ldsm4(af[mi], Ap + aoff[mi] + kadd);
            #pragma unroll
            for (int nt = 0; nt < 2; nt++) {
                uint32_t th[4];
                ldsm4(th, Bp + boff[nt] + kadd);
                #pragma unroll
                for (int mi = 0; mi < 4; mi++) {
                    mma_f16(acc[mi][nt*2],   af[mi], &th[0]);
                    mma_f16(acc[mi][nt*2+1], af[mi], &th[2]);
                }
            }
        }
    }

    // epilogue: bias (fp32) + fp16 packed store
    #pragma unroll
    for (int mi = 0; mi < 4; mi++) {
        int row0 = bm0 + m_off + mi * 16 + lg;
        #pragma unroll
        for (int ni = 0; ni < 4; ni++) {
            int col = ncol0 + n_off + ni * 8 + lt * 2;
            float b0 = bias[col], b1 = bias[col + 1];
            if (row0 < ROWS) {
                __half2 h = __floats2half2_rn(acc[mi][ni][0] + b0, acc[mi][ni][1] + b1);
                *reinterpret_cast<__half2*>(&outp[(size_t)row0 * E_ + col]) = h;
            }
            if (row0 + 8 < ROWS) {
                __half2 h = __floats2half2_rn(acc[mi][ni][2] + b0, acc[mi][ni][3] + b1);
                *reinterpret_cast<__half2*>(&outp[(size_t)(row0 + 8) * E_ + col]) = h;
            }
        }
    }
}

// ---------------------------------------------------------------------------
// Kernel 3: window-7 attention + exp-map. R15-exact (frozen optimum):
// TT=16, 256 threads, half2 dots, direct stores.
// ---------------------------------------------------------------------------
#define TT 16
#define STRIP (TT + 2 * W_)   // 22

__global__ __launch_bounds__(256) void attn_kernel(const float* __restrict__ tau,
                                                   float* __restrict__ out)
{
    __shared__ __half sK[STRIP * E_];
    __shared__ __half sV[STRIP * E_];

    int t0 = blockIdx.x * TT;
    int bj = blockIdx.y;
    int base_row = bj * T_;
    int tid = threadIdx.x;

    for (int i = tid; i < STRIP * (E_ / 8); i += 256) {
        int r  = i >> 5;
        int c8 = i & 31;
        int tt = min(max(t0 - W_ + r, 0), T_ - 1);
        size_t g = (size_t)(base_row + tt) * E_ + c8 * 8;
        *reinterpret_cast<uint4*>(&sK[r * E_ + c8 * 8]) =
            *reinterpret_cast<const uint4*>(&g_kh[g]);
        *reinterpret_cast<uint4*>(&sV[r * E_ + c8 * 8]) =
            *reinterpret_cast<const uint4*>(&g_vh[g]);
    }
    __syncthreads();

    int warp = tid >> 5, lane = tid & 31;
    float inv_scale = 1.0f / (16.0f * fmaxf(tau[0], 0.001f));

    #pragma unroll
    for (int s = 0; s < 2; s++) {
        int t = t0 + warp * 2 + s;
        if (t >= T_) continue;
        int lrow = t - t0;

        uint4 qu = *reinterpret_cast<const uint4*>(&g_qh[(size_t)(base_row + t) * E_ + lane * 8]);
        __half2* q2 = reinterpret_cast<__half2*>(&qu);

        float dot[KW_];
        #pragma unroll
        for (int w = 0; w < KW_; w++) {
            uint4 ku = *reinterpret_cast<const uint4*>(&sK[(lrow + w) * E_ + lane * 8]);
            __half2* k2 = reinterpret_cast<__half2*>(&ku);
            __half2 pa = __hmul2(q2[0], k2[0]);
            pa = __hfma2(q2[1], k2[1], pa);
            __half2 pb = __hmul2(q2[2], k2[2]);
            pb = __hfma2(q2[3], k2[3], pb);
            float2 fa = __half22float2(pa);
            float2 fb = __half22float2(pb);
            float d = (fa.x + fa.y) + (fb.x + fb.y);
            #pragma unroll
            for (int o = 16; o > 0; o >>= 1) d += __shfl_xor_sync(0xffffffffu, d, o);
            dot[w] = d;
        }

        float m = -1e30f, logit[KW_];
        #pragma unroll
        for (int w = 0; w < KW_; w++) {
            int tt = t + w - W_;
            bool valid = (tt >= 0) && (tt < T_);
            logit[w] = valid ? dot[w] * inv_scale : -1e30f;
            m = fmaxf(m, logit[w]);
        }
        float e[KW_], esum = 0.f;
        #pragma unroll
        for (int w = 0; w < KW_; w++) {
            int tt = t + w - W_;
            bool valid = (tt >= 0) && (tt < T_);
            e[w] = valid ? __expf(logit[w] - m) : 0.f;
            esum += e[w];
        }
        float inv_esum = 1.0f / esum;

        float agg[8] = {0.f, 0.f, 0.f, 0.f, 0.f, 0.f, 0.f, 0.f};
        #pragma unroll
        for (int w = 0; w < KW_; w++) {
            int tt = t + w - W_;
            if (tt >= 0 && tt < T_) {
                float wt = e[w] * inv_esum;
                uint4 vu = *reinterpret_cast<const uint4*>(&sV[(lrow + w) * E_ + lane * 8]);
                __half2* v2 = reinterpret_cast<__half2*>(&vu);
                #pragma unroll
                for (int p = 0; p < 4; p++) {
                    float2 vf = __half22float2(v2[p]);
                    agg[p*2]   = fmaf(wt, vf.x, agg[p*2]);
                    agg[p*2+1] = fmaf(wt, vf.y, agg[p*2+1]);
                }
            }
        }

        float ss = 0.f;
        #pragma unroll
        for (int i = 0; i < 8; i++) ss = fmaf(agg[i], agg[i], ss);
        #pragma unroll
        for (int o = 16; o > 0; o >>= 1) ss += __shfl_xor_sync(0xffffffffu, ss, o);

        float n = fmaxf(sqrtf(ss), 1e-7f);
        float coef = sinhf(n) / n;
        float ch   = coshf(n);

        int b = bj / J_;
        int j = bj - b * J_;
        size_t obase = ((size_t)(b * T_ + t) * J_ + j) * D_;
        #pragma unroll
        for (int i = 0; i < 8; i++)
            out[obase + 1 + lane * 8 + i] = coef * agg[i];
        if (lane == 0) out[obase] = ch;
    }
}

// ---------------------------------------------------------------------------
extern "C" void kernel_launch(void* const* d_in, const int* in_sizes, int n_in,
                              void* d_out, int out_size)
{
    const float* x    = (const float*)d_in[0];
    // d_in[1] = vel_seq (unused by reference)
    const float* tau  = (const float*)d_in[2];
    const float* Wq   = (const float*)d_in[3];
    const float* bq   = (const float*)d_in[4];
    const float* Wk   = (const float*)d_in[5];
    const float* bk   = (const float*)d_in[6];
    const float* Wv   = (const float*)d_in[7];
    const float* bv   = (const float*)d_in[8];
    float* out = (float*)d_out;

    prep_kernel<<<WBLK + (ROWS + 15) / 16, 256>>>(x, Wq, Wk, Wv);

    cudaFuncSetAttribute(qkv_gemm_tc,
                         cudaFuncAttributeMaxDynamicSharedMemorySize, GEMM_SMEM);
    dim3 g2(6, MTILES);
    qkv_gemm_tc<<<g2, 256, GEMM_SMEM>>>(bq, bk, bv);

    dim3 g3((T_ + TT - 1) / TT, B_ * J_);
    attn_kernel<<<g3, 256>>>(tau, out);
}